// round 16
// baseline (speedup 1.0000x reference)
#include <cuda_runtime.h>
#include <cfloat>

// Caffe-style RoI max pooling, bit-exact to the XLA-executed JAX reference.
//   x: [2,256,64,64] f32, rois: [2048,5] f32 -> out: [2048,256,7,7] f32
// Numerics: bin = roi_dim * RN(1/7) (0x3E124925) — XLA rewrites const-division
// into reciprocal multiply; rintf == jnp.round; __fmul_rn for boundary muls.
//
// Pipeline:
//   K1: transpose x -> xt[b][h][w][c] (channels-last).
//   K2: fused table build: all 8 max tables {1,2,4}^2 \ {1x1} from a 4x4
//       xt neighborhood in registers.
//   K3: pooling. Steps {1,2,4} -> every bin window (<=7/dim) is at most
//       2x2 end-clamped chunks (idempotent max). Phase 1 is BRANCHLESS with
//       setup-precomputed (deduped) chunk pointers and a fully-unrolled
//       7-iteration loop so ptxas can pipeline next-iteration LDGs under
//       the current iteration's fmax/STS (latency was the binding limit).

#define PH 7
#define PW 7
#define SCALE 0.0625f
#define NTHR 256
#define SPITCH 258                 // floats per bin row; stride mod 32 == 2

__device__ float g_xt [2 * 64 * 64 * 256];  // 1x1
__device__ float g_p2 [2 * 64 * 64 * 256];  // 1 row x 2 cols
__device__ float g_p4 [2 * 64 * 64 * 256];  // 1 x 4
__device__ float g_c2 [2 * 64 * 64 * 256];  // 2 x 1
__device__ float g_c4 [2 * 64 * 64 * 256];  // 4 x 1
__device__ float g_r2 [2 * 64 * 64 * 256];  // 2 x 2
__device__ float g_h24[2 * 64 * 64 * 256];  // 2 rows x 4 cols
__device__ float g_h42[2 * 64 * 64 * 256];  // 4 rows x 2 cols
__device__ float g_r4 [2 * 64 * 64 * 256];  // 4 x 4

__device__ __forceinline__ float4 fmax4(float4 a, float4 b) {
    return make_float4(fmaxf(a.x, b.x), fmaxf(a.y, b.y),
                       fmaxf(a.z, b.z), fmaxf(a.w, b.w));
}

// ---- K1: [b][c][hw] -> [b][hw][c] tiled transpose ----
__global__ void __launch_bounds__(256)
transpose_kernel(const float* __restrict__ x)
{
    __shared__ float t[32][33];
    const int tx = threadIdx.x & 31;
    const int ty = threadIdx.x >> 5;
    const int hw0 = blockIdx.x * 32;
    const int c0  = blockIdx.y * 32;
    const int b   = blockIdx.z;
    const float* src = x + (size_t)b * 256 * 4096;
    float* dst = g_xt + (size_t)b * 4096 * 256;

    #pragma unroll
    for (int i = 0; i < 32; i += 8)
        t[ty + i][tx] = src[(size_t)(c0 + ty + i) * 4096 + hw0 + tx];
    __syncthreads();
    #pragma unroll
    for (int i = 0; i < 32; i += 8)
        dst[(size_t)(hw0 + ty + i) * 256 + c0 + tx] = t[tx][ty + i];
}

// ---- K2: fused table build ----
__global__ void __launch_bounds__(256)
build_tables_kernel()
{
    const int idx = blockIdx.x * 256 + threadIdx.x;   // (b,h,w,c4)
    const int c4 = (idx & 63) * 4;
    const int w  = (idx >> 6) & 63;
    const int h  = (idx >> 12) & 63;
    const int b  = idx >> 18;
    const size_t bp = (size_t)b * 4096 * 256;

    const int w1 = min(w + 1, 63), w2 = min(w + 2, 63), w3 = min(w + 3, 63);

    float4 p2r[4], p4r[4], col0[4];
    #pragma unroll
    for (int i = 0; i < 4; ++i) {
        const int hh = min(h + i, 63);
        const float* row = g_xt + bp + ((size_t)(hh * 64)) * 256 + c4;
        const float4 a0 = *(const float4*)(row + (size_t)w  * 256);
        const float4 a1 = *(const float4*)(row + (size_t)w1 * 256);
        const float4 a2 = *(const float4*)(row + (size_t)w2 * 256);
        const float4 a3 = *(const float4*)(row + (size_t)w3 * 256);
        col0[i] = a0;
        p2r[i] = fmax4(a0, a1);
        p4r[i] = fmax4(p2r[i], fmax4(a2, a3));
    }

    const float4 c2  = fmax4(col0[0], col0[1]);
    const float4 c4v = fmax4(c2, fmax4(col0[2], col0[3]));
    const float4 r2  = fmax4(p2r[0], p2r[1]);
    const float4 h42 = fmax4(r2, fmax4(p2r[2], p2r[3]));
    const float4 h24 = fmax4(p4r[0], p4r[1]);
    const float4 r4  = fmax4(h24, fmax4(p4r[2], p4r[3]));

    const size_t o = bp + ((size_t)(h * 64 + w)) * 256 + c4;
    *(float4*)(g_p2  + o) = p2r[0];
    *(float4*)(g_p4  + o) = p4r[0];
    *(float4*)(g_c2  + o) = c2;
    *(float4*)(g_c4  + o) = c4v;
    *(float4*)(g_r2  + o) = r2;
    *(float4*)(g_h24 + o) = h24;
    *(float4*)(g_h42 + o) = h42;
    *(float4*)(g_r4  + o) = r4;
}

// ---- K3: pooling, one block per roi ----
__global__ void __launch_bounds__(NTHR, 4)
roipool_cl_kernel(const float* __restrict__ rois,
                  float* __restrict__ out)
{
    __shared__ float sbin[49 * SPITCH];       // 50.6 KB: [bin][channel]
    __shared__ const float* s_p0[49];
    __shared__ const float* s_p1[49];
    __shared__ const float* s_p2[49];
    __shared__ const float* s_p3[49];
    __shared__ int s_emp[49];

    const int H = 64, W = 64;
    const int r = blockIdx.x;
    const float* roi = rois + (size_t)r * 5;

    // Setup: threads 0..48 compute their bin's 4 (deduped) chunk pointers.
    {
        const int t = threadIdx.x;
        if (t < 49) {
            const int xs = (int)rintf(__fmul_rn(roi[1], SCALE));
            const int ys = (int)rintf(__fmul_rn(roi[2], SCALE));
            const int xe = (int)rintf(__fmul_rn(roi[3], SCALE));
            const int ye = (int)rintf(__fmul_rn(roi[4], SCALE));
            const float roi_w = (float)max(xe - xs + 1, 1);
            const float roi_h = (float)max(ye - ys + 1, 1);
            const float rc7 = __uint_as_float(0x3E124925u);   // RN(1/7)
            const float bw = __fmul_rn(roi_w, rc7);
            const float bh = __fmul_rn(roi_h, rc7);
            const float fph = (float)(t / 7);
            const float fpw = (float)(t % 7);
            const int ws = min(max((int)floorf(__fmul_rn(fpw, bw)) + xs, 0), W);
            const int we = min(max((int)ceilf(__fmul_rn(fpw + 1.0f, bw)) + xs, 0), W);
            const int hs = min(max((int)floorf(__fmul_rn(fph, bh)) + ys, 0), H);
            const int he = min(max((int)ceilf(__fmul_rn(fph + 1.0f, bh)) + ys, 0), H);
            const int nh = he - hs, nw = we - ws;
            const int empty = (nh <= 0) | (nw <= 0);
            const int sh = (nh >= 4) ? 4 : ((nh >= 2) ? 2 : 1);
            const int sw = (nw >= 4) ? 4 : ((nw >= 2) ? 2 : 1);
            const int ih = (nh >= 4) ? 2 : ((nh >= 2) ? 1 : 0);
            const int iw = (nw >= 4) ? 2 : ((nw >= 2) ? 1 : 0);
            const float* tb;
            switch (ih * 3 + iw) {
                case 0: tb = g_xt;  break;
                case 1: tb = g_p2;  break;
                case 2: tb = g_p4;  break;
                case 3: tb = g_c2;  break;
                case 4: tb = g_r2;  break;
                case 5: tb = g_h24; break;
                case 6: tb = g_c4;  break;
                case 7: tb = g_h42; break;
                default: tb = g_r4; break;
            }
            tb += (size_t)((int)roi[0]) * 4096 * 256;
            const int h0 = empty ? 0 : hs;
            const int h1 = empty ? 0 : (he - sh);
            const int w0 = empty ? 0 : ws;
            const int w1 = empty ? 0 : (we - sw);
            s_p0[t] = tb + ((size_t)(h0 * 64 + w0)) * 256;
            s_p1[t] = tb + ((size_t)(h0 * 64 + w1)) * 256;
            s_p2[t] = tb + ((size_t)(h1 * 64 + w0)) * 256;
            s_p3[t] = tb + ((size_t)(h1 * 64 + w1)) * 256;
            s_emp[t] = empty;
        }
    }
    __syncthreads();

    const int wid  = threadIdx.x >> 5;      // 8 warps
    const int lane = threadIdx.x & 31;
    const int lo = 4 * lane;

    // Phase 1: branchless, fully unrolled -> ptxas pipelines next iteration's
    // LDGs under the current iteration's fmax/STS. Duplicate pointers are
    // L1 hits.
    #pragma unroll
    for (int k = 0; k < 7; ++k) {
        const int bin = wid + 8 * k;
        if (bin < 49) {
            const float* p0 = s_p0[bin] + lo;
            const float* p1 = s_p1[bin] + lo;
            const float* p2 = s_p2[bin] + lo;
            const float* p3 = s_p3[bin] + lo;

            const float4 a0 = *(const float4*)p0;
            const float4 a1 = *(const float4*)p1;
            const float4 a2 = *(const float4*)p2;
            const float4 a3 = *(const float4*)p3;
            const float4 b0 = *(const float4*)(p0 + 128);
            const float4 b1 = *(const float4*)(p1 + 128);
            const float4 b2 = *(const float4*)(p2 + 128);
            const float4 b3 = *(const float4*)(p3 + 128);

            float4 m0 = fmax4(fmax4(a0, a1), fmax4(a2, a3));
            float4 m1 = fmax4(fmax4(b0, b1), fmax4(b2, b3));
            if (s_emp[bin]) {
                m0 = make_float4(0.0f, 0.0f, 0.0f, 0.0f);
                m1 = m0;
            }

            float* s = sbin + bin * SPITCH + lo;
            *(float2*)(s)       = make_float2(m0.x, m0.y);
            *(float2*)(s + 2)   = make_float2(m0.z, m0.w);
            *(float2*)(s + 128) = make_float2(m1.x, m1.y);
            *(float2*)(s + 130) = make_float2(m1.z, m1.w);
        }
    }
    __syncthreads();

    // Phase 2: coalesced linear store; (c,bin) maintained incrementally.
    float* out_r = out + (size_t)r * 12544;
    {
        int i = threadIdx.x;
        int c = i / 49;
        int bin = i - c * 49;
        #pragma unroll 1
        for (int k = 0; k < 49; ++k) {
            out_r[i] = sbin[bin * SPITCH + c];
            i += NTHR;
            c += 5; bin += 11;
            if (bin >= 49) { bin -= 49; ++c; }
        }
    }
}

extern "C" void kernel_launch(void* const* d_in, const int* in_sizes, int n_in,
                              void* d_out, int out_size)
{
    const float* x    = (const float*)d_in[0];
    const float* rois = (const float*)d_in[1];
    float* out        = (float*)d_out;
    const int R = in_sizes[1] / 5;

    dim3 tg(128, 8, 2);
    transpose_kernel<<<tg, 256>>>(x);
    build_tables_kernel<<<2048, 256>>>();
    roipool_cl_kernel<<<R, NTHR>>>(rois, out);
}